// round 1
// baseline (speedup 1.0000x reference)
#include <cuda_runtime.h>
#include <math.h>

// ---------------------------------------------------------------------------
// SelfAttentionConv: B=8, T=1024, K=128, H=8, TOP_K=64, KS=5
//
// Pipeline:
//   1) Q/K: causal conv1d (kernel 5)  -> im2col GEMM  M=8192 N=1024 Kr=640
//      V  : pointwise conv            -> GEMM         M=8192 N=1024 Kr=128
//      Epilogue applies bias, scale=128^-0.25, and the reference's scrambled
//      row permutation: row g = b*8192 + t*8 + h (h = c&7, ki = c>>3).
//      K is written TRANSPOSED per pseudo-batch: Kt[p][ki][q].
//   2) S = Q Kt  (64 batched 1024x1024x128 GEMMs) -> g_S (256 MB scratch)
//   3) per-row: exact 64th-largest radix select (full row, pre-mask),
//      floor below-threshold to row min, causal mask, softmax, write back
//   4) O = P V   (64 batched 1024x128x1024 GEMMs)
//   5) out = A Wu^T + bu  (M=8192 N=128 Kr=1024), A gathers O with the
//      inverse permutation.
// ---------------------------------------------------------------------------

#define SCALE_QK 0.2973017787506803f   // 128^-0.25

// scratch (static __device__ allocations are the sanctioned workaround)
__device__ float g_Q  [64 * 1024 * 128];
__device__ float g_Kt [64 * 128 * 1024];
__device__ float g_V  [64 * 1024 * 128];
__device__ float g_O  [64 * 1024 * 128];
__device__ float g_S  [67108864];          // 64 * 1024 * 1024 (256 MB)
__device__ float g_WqT[640 * 1024];
__device__ float g_WkT[640 * 1024];
__device__ float g_WvT[128 * 1024];
__device__ float g_WuT[1024 * 128];

// ---------------- weight transposes ----------------------------------------
__global__ void k_transW5(const float* __restrict__ W, float* __restrict__ Wt) {
    int idx = blockIdx.x * 256 + threadIdx.x;      // over 640*1024
    int k = idx >> 10, c = idx & 1023;
    int j = k >> 7, ci = k & 127;
    Wt[idx] = W[(c * 128 + ci) * 5 + j];           // W: (1024,128,5)
}
__global__ void k_transW1(const float* __restrict__ W, float* __restrict__ Wt) {
    int idx = blockIdx.x * 256 + threadIdx.x;      // over 128*1024
    int ci = idx >> 10, c = idx & 1023;
    Wt[idx] = W[c * 128 + ci];                     // W: (1024,128,1)
}
__global__ void k_transWu(const float* __restrict__ W, float* __restrict__ Wt) {
    int idx = blockIdx.x * 256 + threadIdx.x;      // over 1024*128
    int c = idx >> 7, n = idx & 127;
    Wt[idx] = W[n * 1024 + c];                     // W: (128,1024)
}

// ---------------- conv-as-GEMM (Q / K / V) ----------------------------------
// M=8192 (b,t), N=1024 (c=ki*8+h), A(m,k)=x[b, t+j-pad, ci], k=j*128+ci
__global__ __launch_bounds__(256) void k_conv(
    const float* __restrict__ x, const float* __restrict__ Wt,
    const float* __restrict__ bias, float* __restrict__ out,
    int Kd, int pad, float scale, int transOut)
{
    __shared__ float As[8][128];
    __shared__ float Bs[8][128];
    float acc[8][8];
#pragma unroll
    for (int i = 0; i < 8; i++)
#pragma unroll
        for (int j = 0; j < 8; j++) acc[i][j] = 0.f;

    const int tid = threadIdx.x;
    const int ty = tid >> 4, tx = tid & 15;
    const int rowBase = blockIdx.y * 128;
    const int colBase = blockIdx.x * 128;
    const int lm  = tid >> 1;
    const int lk4 = (tid & 1) * 4;
    const int bk  = tid >> 5;
    const int bn4 = (tid & 31) * 4;
    const int m = rowBase + lm;
    const int b = m >> 10, t = m & 1023;

    for (int kt = 0; kt < Kd; kt += 8) {
        int k4 = kt + lk4;
        int j  = k4 >> 7, ci = k4 & 127;
        int tt = t + j - pad;
        float4 av = make_float4(0.f, 0.f, 0.f, 0.f);
        if (tt >= 0)
            av = *(const float4*)&x[(((b << 10) | tt) << 7) + ci];
        As[lk4 + 0][lm] = av.x; As[lk4 + 1][lm] = av.y;
        As[lk4 + 2][lm] = av.z; As[lk4 + 3][lm] = av.w;
        *(float4*)&Bs[bk][bn4] =
            *(const float4*)&Wt[(kt + bk) * 1024 + colBase + bn4];
        __syncthreads();
#pragma unroll
        for (int kk = 0; kk < 8; kk++) {
            float a[8], bb[8];
            *(float4*)&a[0]  = *(const float4*)&As[kk][ty * 4];
            *(float4*)&a[4]  = *(const float4*)&As[kk][64 + ty * 4];
            *(float4*)&bb[0] = *(const float4*)&Bs[kk][tx * 4];
            *(float4*)&bb[4] = *(const float4*)&Bs[kk][64 + tx * 4];
#pragma unroll
            for (int i = 0; i < 8; i++)
#pragma unroll
                for (int jj = 0; jj < 8; jj++) acc[i][jj] += a[i] * bb[jj];
        }
        __syncthreads();
    }
#pragma unroll
    for (int ii = 0; ii < 8; ii++) {
        int rr = (ii < 4) ? (ty * 4 + ii) : (64 + ty * 4 + ii - 4);
        int mm = rowBase + rr;
        int bb2 = mm >> 10, t2 = mm & 1023;
#pragma unroll
        for (int jj = 0; jj < 8; jj++) {
            int cc = (jj < 4) ? (tx * 4 + jj) : (64 + tx * 4 + jj - 4);
            int cg = colBase + cc;
            int hh = cg & 7, ki = cg >> 3;
            float v = (acc[ii][jj] + bias[cg]) * scale;
            int row = (bb2 << 13) | (t2 << 3) | hh;   // scrambled permutation
            if (!transOut) out[row * 128 + ki] = v;
            else out[((row >> 10) * 128 + ki) * 1024 + (row & 1023)] = v;
        }
    }
}

// ---------------- S = Q * Kt (batched) --------------------------------------
__global__ __launch_bounds__(256) void k_sgemm_s() {
    const int bh = blockIdx.z;
    const float* A = g_Q  + (size_t)bh * (1024 * 128);
    const float* B = g_Kt + (size_t)bh * (128 * 1024);
    float*       C = g_S  + ((size_t)bh << 20);

    __shared__ float As[8][128];
    __shared__ float Bs[8][128];
    float acc[8][8];
#pragma unroll
    for (int i = 0; i < 8; i++)
#pragma unroll
        for (int j = 0; j < 8; j++) acc[i][j] = 0.f;

    const int tid = threadIdx.x;
    const int ty = tid >> 4, tx = tid & 15;
    const int rowBase = blockIdx.y * 128;
    const int colBase = blockIdx.x * 128;
    const int lm = tid >> 1, lk4 = (tid & 1) * 4;
    const int bk = tid >> 5, bn4 = (tid & 31) * 4;

    for (int kt = 0; kt < 128; kt += 8) {
        float4 av = *(const float4*)&A[(rowBase + lm) * 128 + kt + lk4];
        As[lk4 + 0][lm] = av.x; As[lk4 + 1][lm] = av.y;
        As[lk4 + 2][lm] = av.z; As[lk4 + 3][lm] = av.w;
        *(float4*)&Bs[bk][bn4] =
            *(const float4*)&B[(kt + bk) * 1024 + colBase + bn4];
        __syncthreads();
#pragma unroll
        for (int kk = 0; kk < 8; kk++) {
            float a[8], bb[8];
            *(float4*)&a[0]  = *(const float4*)&As[kk][ty * 4];
            *(float4*)&a[4]  = *(const float4*)&As[kk][64 + ty * 4];
            *(float4*)&bb[0] = *(const float4*)&Bs[kk][tx * 4];
            *(float4*)&bb[4] = *(const float4*)&Bs[kk][64 + tx * 4];
#pragma unroll
            for (int i = 0; i < 8; i++)
#pragma unroll
                for (int jj = 0; jj < 8; jj++) acc[i][jj] += a[i] * bb[jj];
        }
        __syncthreads();
    }
#pragma unroll
    for (int ii = 0; ii < 8; ii++) {
        int rr = (ii < 4) ? (ty * 4 + ii) : (64 + ty * 4 + ii - 4);
#pragma unroll
        for (int jj = 0; jj < 8; jj++) {
            int cc = (jj < 4) ? (tx * 4 + jj) : (64 + tx * 4 + jj - 4);
            C[(rowBase + rr) * 1024 + colBase + cc] = acc[ii][jj];
        }
    }
}

// ---------------- per-row top-k threshold + causal softmax ------------------
__global__ __launch_bounds__(256) void k_topk() {
    const int t  = blockIdx.x;
    const int bh = blockIdx.y;
    float* row = g_S + ((size_t)bh << 20) + ((size_t)t << 10);
    const int tid = threadIdx.x;

    float4 v4 = ((const float4*)row)[tid];
    float vals[4] = { v4.x, v4.y, v4.z, v4.w };
    unsigned key[4];
#pragma unroll
    for (int i = 0; i < 4; i++) {
        unsigned u = __float_as_uint(vals[i]);
        key[i] = (u & 0x80000000u) ? ~u : (u | 0x80000000u);
    }

    __shared__ float redf[8];
    // ---- row min ----
    float lmin = fminf(fminf(vals[0], vals[1]), fminf(vals[2], vals[3]));
#pragma unroll
    for (int off = 16; off; off >>= 1)
        lmin = fminf(lmin, __shfl_xor_sync(0xffffffffu, lmin, off));
    if ((tid & 31) == 0) redf[tid >> 5] = lmin;
    __syncthreads();
    float rmin = redf[0];
#pragma unroll
    for (int i = 1; i < 8; i++) rmin = fminf(rmin, redf[i]);

    // ---- radix select: 64th largest key over full row ----
    __shared__ unsigned hist[256];
    __shared__ unsigned scanb[256];
    __shared__ unsigned sh_sel, sh_need;
    unsigned prefix = 0u;
    unsigned need = 64u;
    for (int shift = 24; shift >= 0; shift -= 8) {
        hist[tid] = 0u;
        __syncthreads();
        unsigned mask = (shift == 24) ? 0u : (0xFFFFFFFFu << (shift + 8));
#pragma unroll
        for (int i = 0; i < 4; i++)
            if ((key[i] & mask) == prefix)
                atomicAdd(&hist[(key[i] >> shift) & 255u], 1u);
        __syncthreads();
        scanb[tid] = hist[tid];
        __syncthreads();
        for (int off = 1; off < 256; off <<= 1) {  // inclusive suffix scan
            unsigned add = (tid + off < 256) ? scanb[tid + off] : 0u;
            __syncthreads();
            scanb[tid] += add;
            __syncthreads();
        }
        unsigned cum  = scanb[tid];
        unsigned cumN = (tid < 255) ? scanb[tid + 1] : 0u;
        if (cum >= need && cumN < need) {
            sh_sel = (unsigned)tid;
            sh_need = need - cumN;
        }
        __syncthreads();
        prefix |= (sh_sel << shift);
        need = sh_need;
        __syncthreads();
    }
    unsigned tu = (prefix & 0x80000000u) ? (prefix & 0x7FFFFFFFu) : ~prefix;
    const float thresh = __uint_as_float(tu);

    // ---- threshold, causal mask, softmax over s <= t ----
    float p[4];
    float lmax = -1e30f;
#pragma unroll
    for (int i = 0; i < 4; i++) {
        int s = tid * 4 + i;
        float pv = (vals[i] >= thresh) ? vals[i] : rmin;
        p[i] = pv;
        if (s <= t) lmax = fmaxf(lmax, pv);
    }
#pragma unroll
    for (int off = 16; off; off >>= 1)
        lmax = fmaxf(lmax, __shfl_xor_sync(0xffffffffu, lmax, off));
    if ((tid & 31) == 0) redf[tid >> 5] = lmax;
    __syncthreads();
    float mx = redf[0];
#pragma unroll
    for (int i = 1; i < 8; i++) mx = fmaxf(mx, redf[i]);
    __syncthreads();

    float lsum = 0.f;
#pragma unroll
    for (int i = 0; i < 4; i++) {
        int s = tid * 4 + i;
        if (s <= t) { float e = __expf(p[i] - mx); p[i] = e; lsum += e; }
        else p[i] = 0.f;
    }
#pragma unroll
    for (int off = 16; off; off >>= 1)
        lsum += __shfl_xor_sync(0xffffffffu, lsum, off);
    if ((tid & 31) == 0) redf[tid >> 5] = lsum;
    __syncthreads();
    float tot = 0.f;
#pragma unroll
    for (int i = 0; i < 8; i++) tot += redf[i];
    float inv = 1.f / tot;

    ((float4*)row)[tid] =
        make_float4(p[0] * inv, p[1] * inv, p[2] * inv, p[3] * inv);
}

// ---------------- O = P * V (batched) ---------------------------------------
__global__ __launch_bounds__(256) void k_av() {
    const int bh = blockIdx.z;
    const float* A = g_S + ((size_t)bh << 20);
    const float* B = g_V + (size_t)bh * (1024 * 128);

    __shared__ float As[8][128];
    __shared__ float Bs[8][128];
    float acc[8][8];
#pragma unroll
    for (int i = 0; i < 8; i++)
#pragma unroll
        for (int j = 0; j < 8; j++) acc[i][j] = 0.f;

    const int tid = threadIdx.x;
    const int ty = tid >> 4, tx = tid & 15;
    const int rowBase = blockIdx.y * 128;
    const int lm = tid >> 1, lk4 = (tid & 1) * 4;
    const int bk = tid >> 5, bn4 = (tid & 31) * 4;

    for (int kt = 0; kt < 1024; kt += 8) {
        float4 av = *(const float4*)&A[(rowBase + lm) * 1024 + kt + lk4];
        As[lk4 + 0][lm] = av.x; As[lk4 + 1][lm] = av.y;
        As[lk4 + 2][lm] = av.z; As[lk4 + 3][lm] = av.w;
        *(float4*)&Bs[bk][bn4] = *(const float4*)&B[(kt + bk) * 128 + bn4];
        __syncthreads();
#pragma unroll
        for (int kk = 0; kk < 8; kk++) {
            float a[8], bb[8];
            *(float4*)&a[0]  = *(const float4*)&As[kk][ty * 4];
            *(float4*)&a[4]  = *(const float4*)&As[kk][64 + ty * 4];
            *(float4*)&bb[0] = *(const float4*)&Bs[kk][tx * 4];
            *(float4*)&bb[4] = *(const float4*)&Bs[kk][64 + tx * 4];
#pragma unroll
            for (int i = 0; i < 8; i++)
#pragma unroll
                for (int jj = 0; jj < 8; jj++) acc[i][jj] += a[i] * bb[jj];
        }
        __syncthreads();
    }
#pragma unroll
    for (int ii = 0; ii < 8; ii++) {
        int rr = (ii < 4) ? (ty * 4 + ii) : (64 + ty * 4 + ii - 4);
#pragma unroll
        for (int jj = 0; jj < 8; jj++) {
            int cc = (jj < 4) ? (tx * 4 + jj) : (64 + tx * 4 + jj - 4);
            g_O[((bh << 10) + rowBase + rr) * 128 + cc] = acc[ii][jj];
        }
    }
}

// ---------------- final projection ------------------------------------------
__global__ __launch_bounds__(256) void k_proj(const float* __restrict__ bu,
                                              float* __restrict__ out) {
    __shared__ float As[8][128];
    __shared__ float Bs[8][128];
    float acc[8][8];
#pragma unroll
    for (int i = 0; i < 8; i++)
#pragma unroll
        for (int j = 0; j < 8; j++) acc[i][j] = 0.f;

    const int tid = threadIdx.x;
    const int ty = tid >> 4, tx = tid & 15;
    const int rowBase = blockIdx.y * 128;
    const int lm = tid >> 1, lk4 = (tid & 1) * 4;
    const int bk = tid >> 5, bn4 = (tid & 31) * 4;
    const int m = rowBase + lm;
    const int b = m >> 10, tf = m & 1023;

    for (int kt = 0; kt < 1024; kt += 8) {
        int k4 = kt + lk4;
        int hf = k4 >> 7, ki = k4 & 127;
        float4 av = *(const float4*)
            &g_O[(((b << 13) + (hf << 10) + tf) << 7) + ki];
        As[lk4 + 0][lm] = av.x; As[lk4 + 1][lm] = av.y;
        As[lk4 + 2][lm] = av.z; As[lk4 + 3][lm] = av.w;
        *(float4*)&Bs[bk][bn4] =
            *(const float4*)&g_WuT[(kt + bk) * 128 + bn4];
        __syncthreads();
#pragma unroll
        for (int kk = 0; kk < 8; kk++) {
            float a[8], bb[8];
            *(float4*)&a[0]  = *(const float4*)&As[kk][ty * 4];
            *(float4*)&a[4]  = *(const float4*)&As[kk][64 + ty * 4];
            *(float4*)&bb[0] = *(const float4*)&Bs[kk][tx * 4];
            *(float4*)&bb[4] = *(const float4*)&Bs[kk][64 + tx * 4];
#pragma unroll
            for (int i = 0; i < 8; i++)
#pragma unroll
                for (int jj = 0; jj < 8; jj++) acc[i][jj] += a[i] * bb[jj];
        }
        __syncthreads();
    }
#pragma unroll
    for (int ii = 0; ii < 8; ii++) {
        int rr = (ii < 4) ? (ty * 4 + ii) : (64 + ty * 4 + ii - 4);
#pragma unroll
        for (int jj = 0; jj < 8; jj++) {
            int cc = (jj < 4) ? (tx * 4 + jj) : (64 + tx * 4 + jj - 4);
            out[(rowBase + rr) * 128 + cc] = acc[ii][jj] + bu[cc];
        }
    }
}

// ---------------------------------------------------------------------------
extern "C" void kernel_launch(void* const* d_in, const int* in_sizes, int n_in,
                              void* d_out, int out_size) {
    const float* x  = (const float*)d_in[0];
    const float* Wq = (const float*)d_in[1];
    const float* bq = (const float*)d_in[2];
    const float* Wk = (const float*)d_in[3];
    const float* bk = (const float*)d_in[4];
    const float* Wv = (const float*)d_in[5];
    const float* bv = (const float*)d_in[6];
    const float* Wu = (const float*)d_in[7];
    const float* bu = (const float*)d_in[8];
    float* out = (float*)d_out;

    float *pWqT, *pWkT, *pWvT, *pWuT, *pQ, *pKt, *pV;
    cudaGetSymbolAddress((void**)&pWqT, g_WqT);
    cudaGetSymbolAddress((void**)&pWkT, g_WkT);
    cudaGetSymbolAddress((void**)&pWvT, g_WvT);
    cudaGetSymbolAddress((void**)&pWuT, g_WuT);
    cudaGetSymbolAddress((void**)&pQ,  g_Q);
    cudaGetSymbolAddress((void**)&pKt, g_Kt);
    cudaGetSymbolAddress((void**)&pV,  g_V);

    k_transW5<<<2560, 256>>>(Wq, pWqT);
    k_transW5<<<2560, 256>>>(Wk, pWkT);
    k_transW1<<<512, 256>>>(Wv, pWvT);
    k_transWu<<<512, 256>>>(Wu, pWuT);

    dim3 gConv(8, 64);
    k_conv<<<gConv, 256>>>(x, pWqT, bq, pQ,  640, 4, SCALE_QK, 0);
    k_conv<<<gConv, 256>>>(x, pWkT, bk, pKt, 640, 4, SCALE_QK, 1);
    k_conv<<<gConv, 256>>>(x, pWvT, bv, pV,  128, 0, 1.0f,     0);

    k_sgemm_s<<<dim3(8, 8, 64), 256>>>();
    k_topk<<<dim3(1024, 64), 256>>>();
    k_av<<<dim3(1, 8, 64), 256>>>();
    k_proj<<<dim3(1, 64), 256>>>(bu, out);
}

// round 2
// speedup vs baseline: 1.2196x; 1.2196x over previous
#include <cuda_runtime.h>
#include <math.h>

// ---------------------------------------------------------------------------
// SelfAttentionConv: B=8, T=1024, K=128, H=8, TOP_K=64, KS=5
// Round 2: all GEMMs use packed fma.rn.f32x2 (FFMA2) with A-dup smem tiles,
// double-buffered smem (1 sync/step), causal K-bound on P*V, shfl-scan topk.
// ---------------------------------------------------------------------------

#define SCALE_QK 0.2973017787506803f   // 128^-0.25

__device__ float g_Q  [64 * 1024 * 128];
__device__ float g_Kt [64 * 128 * 1024];
__device__ float g_V  [64 * 1024 * 128];
__device__ float g_O  [64 * 1024 * 128];
__device__ float g_S  [67108864];          // 64 * 1024 * 1024 (256 MB)
__device__ float g_WqT[640 * 1024];
__device__ float g_WkT[640 * 1024];
__device__ float g_WvT[128 * 1024];
__device__ float g_WuT[1024 * 128];

// ---------------- packed-fp32 helpers ---------------------------------------
__device__ __forceinline__ unsigned long long fma2(unsigned long long a,
                                                   unsigned long long b,
                                                   unsigned long long c) {
    unsigned long long d;
    asm("fma.rn.f32x2 %0, %1, %2, %3;" : "=l"(d) : "l"(a), "l"(b), "l"(c));
    return d;
}
__device__ __forceinline__ float2 up2(unsigned long long v) {
    float2 r;
    asm("mov.b64 {%0, %1}, %2;" : "=f"(r.x), "=f"(r.y) : "l"(v));
    return r;
}

// core 8x8 micro-tile step over an 8-deep smem tile.
// As: [8][128] float2 (value duplicated in both halves), Bs: [8][128] float.
__device__ __forceinline__ void mm_step(const float2* __restrict__ As,
                                        const float*  __restrict__ Bs,
                                        int ty, int tx,
                                        unsigned long long acc[8][4]) {
#pragma unroll
    for (int kk = 0; kk < 8; kk++) {
        const float2* ar = As + kk * 128;
        const float*  br = Bs + kk * 128;
        ulonglong2 a01 = *(const ulonglong2*)(ar + ty * 4);
        ulonglong2 a23 = *(const ulonglong2*)(ar + ty * 4 + 2);
        ulonglong2 a45 = *(const ulonglong2*)(ar + 64 + ty * 4);
        ulonglong2 a67 = *(const ulonglong2*)(ar + 64 + ty * 4 + 2);
        ulonglong2 b01 = *(const ulonglong2*)(br + tx * 4);
        ulonglong2 b23 = *(const ulonglong2*)(br + 64 + tx * 4);
        unsigned long long a[8] = {a01.x, a01.y, a23.x, a23.y,
                                   a45.x, a45.y, a67.x, a67.y};
        unsigned long long b[4] = {b01.x, b01.y, b23.x, b23.y};
#pragma unroll
        for (int i = 0; i < 8; i++)
#pragma unroll
            for (int p = 0; p < 4; p++)
                acc[i][p] = fma2(a[i], b[p], acc[i][p]);
    }
}

// column-pair base for acc[i][p]
__device__ __forceinline__ int colpair(int tx, int p) {
    return ((p >> 1) ? 64 : 0) + tx * 4 + (p & 1) * 2;
}
__device__ __forceinline__ int rowidx(int ty, int i) {
    return (i < 4) ? (ty * 4 + i) : (64 + ty * 4 + i - 4);
}

// ---------------- merged weight prep ----------------------------------------
__global__ void k_prep(const float* __restrict__ Wq, const float* __restrict__ Wk,
                       const float* __restrict__ Wv, const float* __restrict__ Wu,
                       float* __restrict__ WqT, float* __restrict__ WkT,
                       float* __restrict__ WvT, float* __restrict__ WuT) {
    int idx = blockIdx.x * 256 + threadIdx.x;        // 0 .. 1572863
    if (idx < 655360) {
        int k = idx >> 10, c = idx & 1023;
        int j = k >> 7, ci = k & 127;
        WqT[idx] = Wq[(c * 128 + ci) * 5 + j];
    } else if (idx < 1310720) {
        int i1 = idx - 655360;
        int k = i1 >> 10, c = i1 & 1023;
        int j = k >> 7, ci = k & 127;
        WkT[i1] = Wk[(c * 128 + ci) * 5 + j];
    } else if (idx < 1441792) {
        int i2 = idx - 1310720;
        int ci = i2 >> 10, c = i2 & 1023;
        WvT[i2] = Wv[c * 128 + ci];
    } else {
        int i3 = idx - 1441792;
        int c = i3 >> 7, n = i3 & 127;
        WuT[i3] = Wu[n * 1024 + c];
    }
}

// ---------------- conv-as-GEMM (Q / K / V) ----------------------------------
__global__ __launch_bounds__(256, 2) void k_conv(
    const float* __restrict__ x, const float* __restrict__ Wt,
    const float* __restrict__ bias, float* __restrict__ out,
    int Kd, int pad, float scale, int transOut)
{
    __shared__ __align__(16) float2 Asd[2][8][128];
    __shared__ __align__(16) float  Bs [2][8][128];
    unsigned long long acc[8][4];
#pragma unroll
    for (int i = 0; i < 8; i++)
#pragma unroll
        for (int p = 0; p < 4; p++) acc[i][p] = 0ull;

    const int tid = threadIdx.x;
    const int ty = tid >> 4, tx = tid & 15;
    const int rowBase = blockIdx.y * 128;
    const int colBase = blockIdx.x * 128;
    const int lm = tid >> 1, lk4 = (tid & 1) * 4;
    const int bk = tid >> 5, bn4 = (tid & 31) * 4;
    const int m = rowBase + lm;
    const int b = m >> 10, t = m & 1023;

    float4 av, bv;
    {   // tile 0
        int k4 = lk4;
        int j = k4 >> 7, ci = k4 & 127;
        int tt = t + j - pad;
        av = make_float4(0.f, 0.f, 0.f, 0.f);
        if (tt >= 0) av = *(const float4*)&x[(((b << 10) | tt) << 7) + ci];
        bv = *(const float4*)&Wt[bk * 1024 + colBase + bn4];
    }
    Asd[0][lk4 + 0][lm] = make_float2(av.x, av.x);
    Asd[0][lk4 + 1][lm] = make_float2(av.y, av.y);
    Asd[0][lk4 + 2][lm] = make_float2(av.z, av.z);
    Asd[0][lk4 + 3][lm] = make_float2(av.w, av.w);
    *(float4*)&Bs[0][bk][bn4] = bv;
    __syncthreads();

    int buf = 0;
    for (int kt = 8; kt < Kd; kt += 8) {
        int k4 = kt + lk4;
        int j = k4 >> 7, ci = k4 & 127;
        int tt = t + j - pad;
        av = make_float4(0.f, 0.f, 0.f, 0.f);
        if (tt >= 0) av = *(const float4*)&x[(((b << 10) | tt) << 7) + ci];
        bv = *(const float4*)&Wt[(kt + bk) * 1024 + colBase + bn4];

        mm_step(&Asd[buf][0][0], &Bs[buf][0][0], ty, tx, acc);
        buf ^= 1;
        Asd[buf][lk4 + 0][lm] = make_float2(av.x, av.x);
        Asd[buf][lk4 + 1][lm] = make_float2(av.y, av.y);
        Asd[buf][lk4 + 2][lm] = make_float2(av.z, av.z);
        Asd[buf][lk4 + 3][lm] = make_float2(av.w, av.w);
        *(float4*)&Bs[buf][bk][bn4] = bv;
        __syncthreads();
    }
    mm_step(&Asd[buf][0][0], &Bs[buf][0][0], ty, tx, acc);

#pragma unroll
    for (int i = 0; i < 8; i++) {
        int rr = rowidx(ty, i);
        int mm = rowBase + rr;
        int b2 = mm >> 10, t2 = mm & 1023;
        int gb = (b2 << 13) | (t2 << 3);
#pragma unroll
        for (int p = 0; p < 4; p++) {
            float2 v = up2(acc[i][p]);
            int cc0 = colBase + colpair(tx, p);
#pragma unroll
            for (int e = 0; e < 2; e++) {
                int cg = cc0 + e;
                float val = ((e ? v.y : v.x) + bias[cg]) * scale;
                int hh = cg & 7, ki = cg >> 3;
                int row = gb | hh;
                if (!transOut) out[row * 128 + ki] = val;
                else out[((row >> 10) * 128 + ki) * 1024 + (row & 1023)] = val;
            }
        }
    }
}

// ---------------- S = Q * Kt (batched) --------------------------------------
__global__ __launch_bounds__(256, 2) void k_sgemm_s() {
    const int bh = blockIdx.z;
    const float* A = g_Q  + (size_t)bh * (1024 * 128);
    const float* B = g_Kt + (size_t)bh * (128 * 1024);
    float*       C = g_S  + ((size_t)bh << 20);

    __shared__ __align__(16) float2 Asd[2][8][128];
    __shared__ __align__(16) float  Bs [2][8][128];
    unsigned long long acc[8][4];
#pragma unroll
    for (int i = 0; i < 8; i++)
#pragma unroll
        for (int p = 0; p < 4; p++) acc[i][p] = 0ull;

    const int tid = threadIdx.x;
    const int ty = tid >> 4, tx = tid & 15;
    const int rowBase = blockIdx.y * 128;
    const int colBase = blockIdx.x * 128;
    const int lm = tid >> 1, lk4 = (tid & 1) * 4;
    const int bk = tid >> 5, bn4 = (tid & 31) * 4;

    float4 av = *(const float4*)&A[(rowBase + lm) * 128 + lk4];
    float4 bv = *(const float4*)&B[bk * 1024 + colBase + bn4];
    Asd[0][lk4 + 0][lm] = make_float2(av.x, av.x);
    Asd[0][lk4 + 1][lm] = make_float2(av.y, av.y);
    Asd[0][lk4 + 2][lm] = make_float2(av.z, av.z);
    Asd[0][lk4 + 3][lm] = make_float2(av.w, av.w);
    *(float4*)&Bs[0][bk][bn4] = bv;
    __syncthreads();

    int buf = 0;
#pragma unroll 4
    for (int kt = 8; kt < 128; kt += 8) {
        av = *(const float4*)&A[(rowBase + lm) * 128 + kt + lk4];
        bv = *(const float4*)&B[(kt + bk) * 1024 + colBase + bn4];
        mm_step(&Asd[buf][0][0], &Bs[buf][0][0], ty, tx, acc);
        buf ^= 1;
        Asd[buf][lk4 + 0][lm] = make_float2(av.x, av.x);
        Asd[buf][lk4 + 1][lm] = make_float2(av.y, av.y);
        Asd[buf][lk4 + 2][lm] = make_float2(av.z, av.z);
        Asd[buf][lk4 + 3][lm] = make_float2(av.w, av.w);
        *(float4*)&Bs[buf][bk][bn4] = bv;
        __syncthreads();
    }
    mm_step(&Asd[buf][0][0], &Bs[buf][0][0], ty, tx, acc);

#pragma unroll
    for (int i = 0; i < 8; i++) {
        int rr = rowidx(ty, i);
#pragma unroll
        for (int p = 0; p < 4; p++) {
            float2 v = up2(acc[i][p]);
            int cc0 = colBase + colpair(tx, p);
            *(float2*)&C[(rowBase + rr) * 1024 + cc0] = v;
        }
    }
}

// ---------------- per-row top-k threshold + causal softmax ------------------
__global__ __launch_bounds__(256) void k_topk() {
    const int t  = blockIdx.x;
    const int bh = blockIdx.y;
    float* row = g_S + ((size_t)bh << 20) + ((size_t)t << 10);
    const int tid = threadIdx.x, lane = tid & 31, wid = tid >> 5;

    float4 v4 = ((const float4*)row)[tid];
    float vals[4] = { v4.x, v4.y, v4.z, v4.w };
    unsigned key[4];
#pragma unroll
    for (int i = 0; i < 4; i++) {
        unsigned u = __float_as_uint(vals[i]);
        key[i] = (u & 0x80000000u) ? ~u : (u | 0x80000000u);
    }

    __shared__ float redf[8];
    __shared__ unsigned hist[256];
    __shared__ unsigned wsum[8];
    __shared__ unsigned sh_sel, sh_need;

    // ---- row min ----
    float lmin = fminf(fminf(vals[0], vals[1]), fminf(vals[2], vals[3]));
#pragma unroll
    for (int off = 16; off; off >>= 1)
        lmin = fminf(lmin, __shfl_xor_sync(0xffffffffu, lmin, off));
    if (lane == 0) redf[wid] = lmin;
    __syncthreads();
    float rmin = redf[0];
#pragma unroll
    for (int i = 1; i < 8; i++) rmin = fminf(rmin, redf[i]);

    // ---- radix select: exact 64th-largest key over full row ----
    unsigned prefix = 0u, need = 64u;
#pragma unroll
    for (int pass = 0; pass < 4; pass++) {
        const int shift = 24 - pass * 8;
        hist[tid] = 0u;
        __syncthreads();
        unsigned mask = (pass == 0) ? 0u : (0xFFFFFFFFu << (shift + 8));
#pragma unroll
        for (int i = 0; i < 4; i++)
            if ((key[i] & mask) == prefix)
                atomicAdd(&hist[(key[i] >> shift) & 255u], 1u);
        __syncthreads();
        unsigned h = hist[tid];
        unsigned s = h;
#pragma unroll
        for (int off = 1; off < 32; off <<= 1) {
            unsigned v = __shfl_down_sync(0xffffffffu, s, off);
            if (lane + off < 32) s += v;
        }
        if (lane == 0) wsum[wid] = s;
        __syncthreads();
        unsigned tail = 0u;
        for (int w = wid + 1; w < 8; w++) tail += wsum[w];
        unsigned cum = s + tail;          // inclusive suffix sum from bin tid
        unsigned cumN = cum - h;          // suffix from bin tid+1
        if (cum >= need && cumN < need) { sh_sel = (unsigned)tid; sh_need = need - cumN; }
        __syncthreads();
        prefix |= (sh_sel << shift);
        need = sh_need;
        __syncthreads();
    }
    unsigned tu = (prefix & 0x80000000u) ? (prefix & 0x7FFFFFFFu) : ~prefix;
    const float thresh = __uint_as_float(tu);

    // ---- threshold, causal mask, softmax over s <= t ----
    float p[4];
    float lmax = -1e30f;
#pragma unroll
    for (int i = 0; i < 4; i++) {
        int s = tid * 4 + i;
        float pv = (vals[i] >= thresh) ? vals[i] : rmin;
        p[i] = pv;
        if (s <= t) lmax = fmaxf(lmax, pv);
    }
#pragma unroll
    for (int off = 16; off; off >>= 1)
        lmax = fmaxf(lmax, __shfl_xor_sync(0xffffffffu, lmax, off));
    if (lane == 0) redf[wid] = lmax;
    __syncthreads();
    float mx = redf[0];
#pragma unroll
    for (int i = 1; i < 8; i++) mx = fmaxf(mx, redf[i]);
    __syncthreads();

    float lsum = 0.f;
#pragma unroll
    for (int i = 0; i < 4; i++) {
        int s = tid * 4 + i;
        if (s <= t) { float e = __expf(p[i] - mx); p[i] = e; lsum += e; }
        else p[i] = 0.f;
    }
#pragma unroll
    for (int off = 16; off; off >>= 1)
        lsum += __shfl_xor_sync(0xffffffffu, lsum, off);
    if (lane == 0) redf[wid] = lsum;
    __syncthreads();
    float tot = 0.f;
#pragma unroll
    for (int i = 0; i < 8; i++) tot += redf[i];
    float inv = 1.f / tot;

    ((float4*)row)[tid] =
        make_float4(p[0] * inv, p[1] * inv, p[2] * inv, p[3] * inv);
}

// ---------------- O = P * V (batched, causal K-bound) ------------------------
__global__ __launch_bounds__(256, 2) void k_av() {
    const int bh = blockIdx.y;
    const int rowBase = blockIdx.x * 128;
    const float* A = g_S + ((size_t)bh << 20);
    const float* B = g_V + (size_t)bh * (1024 * 128);

    __shared__ __align__(16) float2 Asd[2][8][128];
    __shared__ __align__(16) float  Bs [2][8][128];
    unsigned long long acc[8][4];
#pragma unroll
    for (int i = 0; i < 8; i++)
#pragma unroll
        for (int p = 0; p < 4; p++) acc[i][p] = 0ull;

    const int tid = threadIdx.x;
    const int ty = tid >> 4, tx = tid & 15;
    const int lm = tid >> 1, lk4 = (tid & 1) * 4;
    const int bk = tid >> 5, bn4 = (tid & 31) * 4;
    const int kEnd = rowBase + 128;   // P[t][s] == 0 for s > t

    float4 av = *(const float4*)&A[(rowBase + lm) * 1024 + lk4];
    float4 bv = *(const float4*)&B[bk * 128 + bn4];
    Asd[0][lk4 + 0][lm] = make_float2(av.x, av.x);
    Asd[0][lk4 + 1][lm] = make_float2(av.y, av.y);
    Asd[0][lk4 + 2][lm] = make_float2(av.z, av.z);
    Asd[0][lk4 + 3][lm] = make_float2(av.w, av.w);
    *(float4*)&Bs[0][bk][bn4] = bv;
    __syncthreads();

    int buf = 0;
    for (int kt = 8; kt < kEnd; kt += 8) {
        av = *(const float4*)&A[(rowBase + lm) * 1024 + kt + lk4];
        bv = *(const float4*)&B[(kt + bk) * 128 + bn4];
        mm_step(&Asd[buf][0][0], &Bs[buf][0][0], ty, tx, acc);
        buf ^= 1;
        Asd[buf][lk4 + 0][lm] = make_float2(av.x, av.x);
        Asd[buf][lk4 + 1][lm] = make_float2(av.y, av.y);
        Asd[buf][lk4 + 2][lm] = make_float2(av.z, av.z);
        Asd[buf][lk4 + 3][lm] = make_float2(av.w, av.w);
        *(float4*)&Bs[buf][bk][bn4] = bv;
        __syncthreads();
    }
    mm_step(&Asd[buf][0][0], &Bs[buf][0][0], ty, tx, acc);

#pragma unroll
    for (int i = 0; i < 8; i++) {
        int rr = rowidx(ty, i);
#pragma unroll
        for (int p = 0; p < 4; p++) {
            float2 v = up2(acc[i][p]);
            int cc0 = colpair(tx, p);
            *(float2*)&g_O[(size_t)((bh << 10) + rowBase + rr) * 128 + cc0] = v;
        }
    }
}

// ---------------- final projection ------------------------------------------
__global__ __launch_bounds__(256, 2) void k_proj(const float* __restrict__ bu,
                                                 float* __restrict__ out) {
    __shared__ __align__(16) float2 Asd[2][8][128];
    __shared__ __align__(16) float  Bs [2][8][128];
    unsigned long long acc[8][4];
#pragma unroll
    for (int i = 0; i < 8; i++)
#pragma unroll
        for (int p = 0; p < 4; p++) acc[i][p] = 0ull;

    const int tid = threadIdx.x;
    const int ty = tid >> 4, tx = tid & 15;
    const int rowBase = blockIdx.x * 128;
    const int lm = tid >> 1, lk4 = (tid & 1) * 4;
    const int bk = tid >> 5, bn4 = (tid & 31) * 4;
    const int m = rowBase + lm;
    const int b = m >> 10, tf = m & 1023;

    float4 av, bv;
    {
        int k4 = lk4;
        int hf = k4 >> 7, ki = k4 & 127;
        av = *(const float4*)&g_O[(size_t)(((b << 13) + (hf << 10) + tf) << 7) + ki];
        bv = *(const float4*)&g_WuT[bk * 128 + bn4];
    }
    Asd[0][lk4 + 0][lm] = make_float2(av.x, av.x);
    Asd[0][lk4 + 1][lm] = make_float2(av.y, av.y);
    Asd[0][lk4 + 2][lm] = make_float2(av.z, av.z);
    Asd[0][lk4 + 3][lm] = make_float2(av.w, av.w);
    *(float4*)&Bs[0][bk][bn4] = bv;
    __syncthreads();

    int buf = 0;
    for (int kt = 8; kt < 1024; kt += 8) {
        int k4 = kt + lk4;
        int hf = k4 >> 7, ki = k4 & 127;
        av = *(const float4*)&g_O[(size_t)(((b << 13) + (hf << 10) + tf) << 7) + ki];
        bv = *(const float4*)&g_WuT[(kt + bk) * 128 + bn4];
        mm_step(&Asd[buf][0][0], &Bs[buf][0][0], ty, tx, acc);
        buf ^= 1;
        Asd[buf][lk4 + 0][lm] = make_float2(av.x, av.x);
        Asd[buf][lk4 + 1][lm] = make_float2(av.y, av.y);
        Asd[buf][lk4 + 2][lm] = make_float2(av.z, av.z);
        Asd[buf][lk4 + 3][lm] = make_float2(av.w, av.w);
        *(float4*)&Bs[buf][bk][bn4] = bv;
        __syncthreads();
    }
    mm_step(&Asd[buf][0][0], &Bs[buf][0][0], ty, tx, acc);

#pragma unroll
    for (int i = 0; i < 8; i++) {
        int rr = rowidx(ty, i);
#pragma unroll
        for (int p = 0; p < 4; p++) {
            float2 v = up2(acc[i][p]);
            int cc0 = colpair(tx, p);
            v.x += bu[cc0];
            v.y += bu[cc0 + 1];
            *(float2*)&out[(rowBase + rr) * 128 + cc0] = v;
        }
    }
}

// ---------------------------------------------------------------------------
extern "C" void kernel_launch(void* const* d_in, const int* in_sizes, int n_in,
                              void* d_out, int out_size) {
    const float* x  = (const float*)d_in[0];
    const float* Wq = (const float*)d_in[1];
    const float* bq = (const float*)d_in[2];
    const float* Wk = (const float*)d_in[3];
    const float* bk = (const float*)d_in[4];
    const float* Wv = (const float*)d_in[5];
    const float* bv = (const float*)d_in[6];
    const float* Wu = (const float*)d_in[7];
    const float* bu = (const float*)d_in[8];
    float* out = (float*)d_out;

    float *pWqT, *pWkT, *pWvT, *pWuT, *pQ, *pKt, *pV;
    cudaGetSymbolAddress((void**)&pWqT, g_WqT);
    cudaGetSymbolAddress((void**)&pWkT, g_WkT);
    cudaGetSymbolAddress((void**)&pWvT, g_WvT);
    cudaGetSymbolAddress((void**)&pWuT, g_WuT);
    cudaGetSymbolAddress((void**)&pQ,  g_Q);
    cudaGetSymbolAddress((void**)&pKt, g_Kt);
    cudaGetSymbolAddress((void**)&pV,  g_V);

    k_prep<<<6144, 256>>>(Wq, Wk, Wv, Wu, pWqT, pWkT, pWvT, pWuT);

    dim3 gConv(8, 64);
    k_conv<<<gConv, 256>>>(x, pWqT, bq, pQ,  640, 4, SCALE_QK, 0);
    k_conv<<<gConv, 256>>>(x, pWkT, bk, pKt, 640, 4, SCALE_QK, 1);
    k_conv<<<gConv, 256>>>(x, pWvT, bv, pV,  128, 0, 1.0f,     0);

    k_sgemm_s<<<dim3(8, 8, 64), 256>>>();
    k_topk<<<dim3(1024, 64), 256>>>();
    k_av<<<dim3(8, 64), 256>>>();
    k_proj<<<64, 256>>>(bu, out);
}

// round 3
// speedup vs baseline: 1.4160x; 1.1611x over previous
#include <cuda_runtime.h>
#include <math.h>

// ---------------------------------------------------------------------------
// SelfAttentionConv: B=8, T=1024, K=128, H=8, TOP_K=64, KS=5
// Round 3: non-duplicated A smem tiles (mov.b64 pack), stats-only topk with
// softmax folded into the P*V A-loads, float4 coalesced epilogues, merged
// Q+K conv launch.
// ---------------------------------------------------------------------------

#define SCALE_QK 0.2973017787506803f   // 128^-0.25

__device__ float g_Q    [64 * 1024 * 128];
__device__ float g_Kt   [64 * 128 * 1024];
__device__ float g_V    [64 * 1024 * 128];
__device__ float g_O    [64 * 1024 * 128];
__device__ float g_S    [67108864];        // 64 * 1024 * 1024
__device__ float g_stats[65536 * 4];       // per-row: thresh, rmin, off, pad
__device__ float g_WqT  [640 * 1024];
__device__ float g_WkT  [640 * 1024];
__device__ float g_WvT  [128 * 1024];
__device__ float g_WuT  [1024 * 128];

// ---------------- packed-fp32 helpers ---------------------------------------
__device__ __forceinline__ unsigned long long fma2(unsigned long long a,
                                                   unsigned long long b,
                                                   unsigned long long c) {
    unsigned long long d;
    asm("fma.rn.f32x2 %0, %1, %2, %3;" : "=l"(d) : "l"(a), "l"(b), "l"(c));
    return d;
}
__device__ __forceinline__ float2 up2(unsigned long long v) {
    float2 r;
    asm("mov.b64 {%0, %1}, %2;" : "=f"(r.x), "=f"(r.y) : "l"(v));
    return r;
}
__device__ __forceinline__ unsigned long long dup2(float a) {
    unsigned long long d;
    asm("mov.b64 %0, {%1, %1};" : "=l"(d) : "f"(a));
    return d;
}

// core 8x8 micro-tile step over an 8-deep smem tile (plain-float A tile).
__device__ __forceinline__ void mm_step(const float* __restrict__ As,
                                        const float* __restrict__ Bs,
                                        int ty, int tx,
                                        unsigned long long acc[8][4]) {
#pragma unroll
    for (int kk = 0; kk < 8; kk++) {
        const float* ar = As + kk * 128;
        const float* br = Bs + kk * 128;
        float4 x0 = *(const float4*)(ar + ty * 4);
        float4 x1 = *(const float4*)(ar + 64 + ty * 4);
        ulonglong2 b01 = *(const ulonglong2*)(br + tx * 4);
        ulonglong2 b23 = *(const ulonglong2*)(br + 64 + tx * 4);
        unsigned long long a[8] = {dup2(x0.x), dup2(x0.y), dup2(x0.z), dup2(x0.w),
                                   dup2(x1.x), dup2(x1.y), dup2(x1.z), dup2(x1.w)};
        unsigned long long b[4] = {b01.x, b01.y, b23.x, b23.y};
#pragma unroll
        for (int i = 0; i < 8; i++)
#pragma unroll
            for (int p = 0; p < 4; p++)
                acc[i][p] = fma2(a[i], b[p], acc[i][p]);
    }
}

__device__ __forceinline__ int rowidx(int ty, int i) {
    return (i < 4) ? (ty * 4 + i) : (64 + ty * 4 + i - 4);
}
__device__ __forceinline__ float4 packrow(unsigned long long p0,
                                          unsigned long long p1) {
    float2 a = up2(p0), b = up2(p1);
    return make_float4(a.x, a.y, b.x, b.y);
}

// ---------------- merged weight prep ----------------------------------------
__global__ void k_prep(const float* __restrict__ Wq, const float* __restrict__ Wk,
                       const float* __restrict__ Wv, const float* __restrict__ Wu,
                       float* __restrict__ WqT, float* __restrict__ WkT,
                       float* __restrict__ WvT, float* __restrict__ WuT) {
    int idx = blockIdx.x * 256 + threadIdx.x;
    if (idx < 655360) {
        int k = idx >> 10, c = idx & 1023;
        int j = k >> 7, ci = k & 127;
        WqT[idx] = Wq[(c * 128 + ci) * 5 + j];
    } else if (idx < 1310720) {
        int i1 = idx - 655360;
        int k = i1 >> 10, c = i1 & 1023;
        int j = k >> 7, ci = k & 127;
        WkT[i1] = Wk[(c * 128 + ci) * 5 + j];
    } else if (idx < 1441792) {
        int i2 = idx - 1310720;
        int ci = i2 >> 10, c = i2 & 1023;
        WvT[i2] = Wv[c * 128 + ci];
    } else {
        int i3 = idx - 1441792;
        int c = i3 >> 7, n = i3 & 127;
        WuT[i3] = Wu[n * 1024 + c];
    }
}

// ---------------- conv-as-GEMM ------------------------------------------------
// generic body; QK merged kernel uses z to pick weights and transOut.
__device__ __forceinline__ void conv_body(
    const float* __restrict__ x, const float* __restrict__ Wt,
    const float* __restrict__ bias, float* __restrict__ out,
    int Kd, int pad, float scale, int transOut,
    float As[2][8][128], float Bsm[2][8][128])
{
    unsigned long long acc[8][4];
#pragma unroll
    for (int i = 0; i < 8; i++)
#pragma unroll
        for (int p = 0; p < 4; p++) acc[i][p] = 0ull;

    const int tid = threadIdx.x;
    const int ty = tid >> 4, tx = tid & 15;
    const int rowBase = blockIdx.y * 128;
    const int colBase = blockIdx.x * 128;
    const int lm = tid >> 1, lk4 = (tid & 1) * 4;
    const int bk = tid >> 5, bn4 = (tid & 31) * 4;
    const int m = rowBase + lm;
    const int b = m >> 10, t = m & 1023;

    float4 av, bv;
    {
        int j = lk4 >> 7, ci = lk4 & 127;
        int tt = t + j - pad;
        av = make_float4(0.f, 0.f, 0.f, 0.f);
        if (tt >= 0) av = *(const float4*)&x[(((b << 10) | tt) << 7) + ci];
        bv = *(const float4*)&Wt[bk * 1024 + colBase + bn4];
    }
    As[0][lk4 + 0][lm] = av.x; As[0][lk4 + 1][lm] = av.y;
    As[0][lk4 + 2][lm] = av.z; As[0][lk4 + 3][lm] = av.w;
    *(float4*)&Bsm[0][bk][bn4] = bv;
    __syncthreads();

    int buf = 0;
    for (int kt = 8; kt < Kd; kt += 8) {
        int k4 = kt + lk4;
        int j = k4 >> 7, ci = k4 & 127;
        int tt = t + j - pad;
        av = make_float4(0.f, 0.f, 0.f, 0.f);
        if (tt >= 0) av = *(const float4*)&x[(((b << 10) | tt) << 7) + ci];
        bv = *(const float4*)&Wt[(kt + bk) * 1024 + colBase + bn4];

        mm_step(&As[buf][0][0], &Bsm[buf][0][0], ty, tx, acc);
        buf ^= 1;
        As[buf][lk4 + 0][lm] = av.x; As[buf][lk4 + 1][lm] = av.y;
        As[buf][lk4 + 2][lm] = av.z; As[buf][lk4 + 3][lm] = av.w;
        *(float4*)&Bsm[buf][bk][bn4] = bv;
        __syncthreads();
    }
    mm_step(&As[buf][0][0], &Bsm[buf][0][0], ty, tx, acc);

#pragma unroll
    for (int i = 0; i < 8; i++) {
        int rr = rowidx(ty, i);
        int mm = rowBase + rr;
        int b2 = mm >> 10, t2 = mm & 1023;
        int gb = (b2 << 13) | (t2 << 3);
#pragma unroll
        for (int p = 0; p < 4; p++) {
            float2 v = up2(acc[i][p]);
            int cc0 = colBase + ((p >> 1) ? 64 : 0) + tx * 4 + (p & 1) * 2;
#pragma unroll
            for (int e = 0; e < 2; e++) {
                int cg = cc0 + e;
                float val = ((e ? v.y : v.x) + bias[cg]) * scale;
                int hh = cg & 7, ki = cg >> 3;
                int row = gb | hh;
                if (!transOut) out[row * 128 + ki] = val;
                else out[((row >> 10) * 128 + ki) * 1024 + (row & 1023)] = val;
            }
        }
    }
}

__global__ __launch_bounds__(256, 2) void k_convQK(
    const float* __restrict__ x,
    const float* __restrict__ WqT, const float* __restrict__ WkT,
    const float* __restrict__ bq, const float* __restrict__ bk,
    float* __restrict__ Q, float* __restrict__ Kt)
{
    __shared__ __align__(16) float As [2][8][128];
    __shared__ __align__(16) float Bsm[2][8][128];
    if (blockIdx.z == 0)
        conv_body(x, WqT, bq, Q,  640, 4, SCALE_QK, 0, As, Bsm);
    else
        conv_body(x, WkT, bk, Kt, 640, 4, SCALE_QK, 1, As, Bsm);
}

__global__ __launch_bounds__(256, 2) void k_convV(
    const float* __restrict__ x, const float* __restrict__ WvT,
    const float* __restrict__ bv, float* __restrict__ V)
{
    __shared__ __align__(16) float As [2][8][128];
    __shared__ __align__(16) float Bsm[2][8][128];
    conv_body(x, WvT, bv, V, 128, 0, 1.0f, 0, As, Bsm);
}

// ---------------- S = Q * Kt (batched) --------------------------------------
__global__ __launch_bounds__(256, 2) void k_sgemm_s() {
    const int bh = blockIdx.z;
    const float* A = g_Q  + (size_t)bh * (1024 * 128);
    const float* B = g_Kt + (size_t)bh * (128 * 1024);
    float*       C = g_S  + ((size_t)bh << 20);

    __shared__ __align__(16) float As [2][8][128];
    __shared__ __align__(16) float Bsm[2][8][128];
    unsigned long long acc[8][4];
#pragma unroll
    for (int i = 0; i < 8; i++)
#pragma unroll
        for (int p = 0; p < 4; p++) acc[i][p] = 0ull;

    const int tid = threadIdx.x;
    const int ty = tid >> 4, tx = tid & 15;
    const int rowBase = blockIdx.y * 128;
    const int colBase = blockIdx.x * 128;
    const int lm = tid >> 1, lk4 = (tid & 1) * 4;
    const int bk = tid >> 5, bn4 = (tid & 31) * 4;

    float4 av = *(const float4*)&A[(rowBase + lm) * 128 + lk4];
    float4 bv = *(const float4*)&B[bk * 1024 + colBase + bn4];
    As[0][lk4 + 0][lm] = av.x; As[0][lk4 + 1][lm] = av.y;
    As[0][lk4 + 2][lm] = av.z; As[0][lk4 + 3][lm] = av.w;
    *(float4*)&Bsm[0][bk][bn4] = bv;
    __syncthreads();

    int buf = 0;
#pragma unroll 4
    for (int kt = 8; kt < 128; kt += 8) {
        av = *(const float4*)&A[(rowBase + lm) * 128 + kt + lk4];
        bv = *(const float4*)&B[(kt + bk) * 1024 + colBase + bn4];
        mm_step(&As[buf][0][0], &Bsm[buf][0][0], ty, tx, acc);
        buf ^= 1;
        As[buf][lk4 + 0][lm] = av.x; As[buf][lk4 + 1][lm] = av.y;
        As[buf][lk4 + 2][lm] = av.z; As[buf][lk4 + 3][lm] = av.w;
        *(float4*)&Bsm[buf][bk][bn4] = bv;
        __syncthreads();
    }
    mm_step(&As[buf][0][0], &Bsm[buf][0][0], ty, tx, acc);

#pragma unroll
    for (int i = 0; i < 8; i++) {
        int rr = rowidx(ty, i);
        *(float4*)&C[(rowBase + rr) * 1024 + colBase + tx * 4] =
            packrow(acc[i][0], acc[i][1]);
        *(float4*)&C[(rowBase + rr) * 1024 + colBase + 64 + tx * 4] =
            packrow(acc[i][2], acc[i][3]);
    }
}

// ---------------- per-row stats: topk threshold, rmin, softmax offset -------
__global__ __launch_bounds__(256) void k_stats() {
    const int t  = blockIdx.x;
    const int bh = blockIdx.y;
    const float* row = g_S + ((size_t)bh << 20) + ((size_t)t << 10);
    const int tid = threadIdx.x, lane = tid & 31, wid = tid >> 5;

    float4 v4 = ((const float4*)row)[tid];
    float vals[4] = { v4.x, v4.y, v4.z, v4.w };
    unsigned key[4];
#pragma unroll
    for (int i = 0; i < 4; i++) {
        unsigned u = __float_as_uint(vals[i]);
        key[i] = (u & 0x80000000u) ? ~u : (u | 0x80000000u);
    }

    __shared__ float redf[8];
    __shared__ unsigned hist[256];
    __shared__ unsigned wsum[8];
    __shared__ unsigned sh_sel, sh_need;

    float lmin = fminf(fminf(vals[0], vals[1]), fminf(vals[2], vals[3]));
#pragma unroll
    for (int off = 16; off; off >>= 1)
        lmin = fminf(lmin, __shfl_xor_sync(0xffffffffu, lmin, off));
    if (lane == 0) redf[wid] = lmin;
    __syncthreads();
    float rmin = redf[0];
#pragma unroll
    for (int i = 1; i < 8; i++) rmin = fminf(rmin, redf[i]);

    unsigned prefix = 0u, need = 64u;
#pragma unroll
    for (int pass = 0; pass < 4; pass++) {
        const int shift = 24 - pass * 8;
        hist[tid] = 0u;
        __syncthreads();
        unsigned mask = (pass == 0) ? 0u : (0xFFFFFFFFu << (shift + 8));
#pragma unroll
        for (int i = 0; i < 4; i++)
            if ((key[i] & mask) == prefix)
                atomicAdd(&hist[(key[i] >> shift) & 255u], 1u);
        __syncthreads();
        unsigned h = hist[tid];
        unsigned s = h;
#pragma unroll
        for (int off = 1; off < 32; off <<= 1) {
            unsigned v = __shfl_down_sync(0xffffffffu, s, off);
            if (lane + off < 32) s += v;
        }
        if (lane == 0) wsum[wid] = s;
        __syncthreads();
        unsigned tail = 0u;
        for (int w = wid + 1; w < 8; w++) tail += wsum[w];
        unsigned cum = s + tail;
        unsigned cumN = cum - h;
        if (cum >= need && cumN < need) { sh_sel = (unsigned)tid; sh_need = need - cumN; }
        __syncthreads();
        prefix |= (sh_sel << shift);
        need = sh_need;
        __syncthreads();
    }
    unsigned tu = (prefix & 0x80000000u) ? (prefix & 0x7FFFFFFFu) : ~prefix;
    const float thresh = __uint_as_float(tu);

    // max over s<=t of thresholded values
    float p[4];
    float lmax = -1e30f;
#pragma unroll
    for (int i = 0; i < 4; i++) {
        int s = tid * 4 + i;
        float pv = (vals[i] >= thresh) ? vals[i] : rmin;
        p[i] = pv;
        if (s <= t) lmax = fmaxf(lmax, pv);
    }
#pragma unroll
    for (int off = 16; off; off >>= 1)
        lmax = fmaxf(lmax, __shfl_xor_sync(0xffffffffu, lmax, off));
    if (lane == 0) redf[wid] = lmax;
    __syncthreads();
    float mx = redf[0];
#pragma unroll
    for (int i = 1; i < 8; i++) mx = fmaxf(mx, redf[i]);
    __syncthreads();

    float lsum = 0.f;
#pragma unroll
    for (int i = 0; i < 4; i++) {
        int s = tid * 4 + i;
        if (s <= t) lsum += __expf(p[i] - mx);
    }
#pragma unroll
    for (int off = 16; off; off >>= 1)
        lsum += __shfl_xor_sync(0xffffffffu, lsum, off);
    if (lane == 0) redf[wid] = lsum;
    __syncthreads();
    if (tid == 0) {
        float tot = 0.f;
#pragma unroll
        for (int i = 0; i < 8; i++) tot += redf[i];
        float off0 = mx + __logf(tot);
        ((float4*)g_stats)[(bh << 10) + t] = make_float4(thresh, rmin, off0, 0.f);
    }
}

// ---------------- O = P * V, softmax applied on the fly ----------------------
__global__ __launch_bounds__(256, 2) void k_av() {
    const int bh = blockIdx.y;
    const int rowBase = blockIdx.x * 128;
    const float* A = g_S + ((size_t)bh << 20);
    const float* B = g_V + (size_t)bh * (1024 * 128);

    __shared__ __align__(16) float As [2][8][128];
    __shared__ __align__(16) float Bsm[2][8][128];
    unsigned long long acc[8][4];
#pragma unroll
    for (int i = 0; i < 8; i++)
#pragma unroll
        for (int p = 0; p < 4; p++) acc[i][p] = 0ull;

    const int tid = threadIdx.x;
    const int ty = tid >> 4, tx = tid & 15;
    const int lm = tid >> 1, lk4 = (tid & 1) * 4;
    const int bk = tid >> 5, bn4 = (tid & 31) * 4;
    const int kEnd = rowBase + 128;      // P[t][s]==0 for s>t
    const int t = rowBase + lm;

    float4 st = ((const float4*)g_stats)[(bh << 10) + t];
    const float th = st.x, rm = st.y, off0 = st.z;

#define XFORM(raw, sbase)                                                    \
    {                                                                        \
        float* _f = (float*)&raw;                                            \
        _Pragma("unroll")                                                    \
        for (int _i = 0; _i < 4; _i++) {                                     \
            int _s = (sbase) + _i;                                           \
            float _p = (_f[_i] >= th) ? _f[_i] : rm;                         \
            _f[_i] = (_s <= t) ? __expf(_p - off0) : 0.f;                    \
        }                                                                    \
    }

    float4 av = *(const float4*)&A[(size_t)t * 1024 + lk4];
    XFORM(av, lk4);
    float4 bv = *(const float4*)&B[bk * 128 + bn4];
    As[0][lk4 + 0][lm] = av.x; As[0][lk4 + 1][lm] = av.y;
    As[0][lk4 + 2][lm] = av.z; As[0][lk4 + 3][lm] = av.w;
    *(float4*)&Bsm[0][bk][bn4] = bv;
    __syncthreads();

    int buf = 0;
    for (int kt = 8; kt < kEnd; kt += 8) {
        av = *(const float4*)&A[(size_t)t * 1024 + kt + lk4];
        XFORM(av, kt + lk4);
        bv = *(const float4*)&B[(kt + bk) * 128 + bn4];
        mm_step(&As[buf][0][0], &Bsm[buf][0][0], ty, tx, acc);
        buf ^= 1;
        As[buf][lk4 + 0][lm] = av.x; As[buf][lk4 + 1][lm] = av.y;
        As[buf][lk4 + 2][lm] = av.z; As[buf][lk4 + 3][lm] = av.w;
        *(float4*)&Bsm[buf][bk][bn4] = bv;
        __syncthreads();
    }
    mm_step(&As[buf][0][0], &Bsm[buf][0][0], ty, tx, acc);
#undef XFORM

#pragma unroll
    for (int i = 0; i < 8; i++) {
        int rr = rowidx(ty, i);
        size_t rbase = (size_t)((bh << 10) + rowBase + rr) * 128;
        *(float4*)&g_O[rbase + tx * 4]      = packrow(acc[i][0], acc[i][1]);
        *(float4*)&g_O[rbase + 64 + tx * 4] = packrow(acc[i][2], acc[i][3]);
    }
}

// ---------------- final projection ------------------------------------------
__global__ __launch_bounds__(256, 2) void k_proj(const float* __restrict__ bu,
                                                 float* __restrict__ out) {
    __shared__ __align__(16) float As [2][8][128];
    __shared__ __align__(16) float Bsm[2][8][128];
    unsigned long long acc[8][4];
#pragma unroll
    for (int i = 0; i < 8; i++)
#pragma unroll
        for (int p = 0; p < 4; p++) acc[i][p] = 0ull;

    const int tid = threadIdx.x;
    const int ty = tid >> 4, tx = tid & 15;
    const int rowBase = blockIdx.x * 128;
    const int lm = tid >> 1, lk4 = (tid & 1) * 4;
    const int bk = tid >> 5, bn4 = (tid & 31) * 4;
    const int m = rowBase + lm;
    const int b = m >> 10, tf = m & 1023;

    float4 av, bv;
    {
        int hf = lk4 >> 7, ki = lk4 & 127;
        av = *(const float4*)&g_O[(size_t)(((b << 13) + (hf << 10) + tf) << 7) + ki];
        bv = *(const float4*)&g_WuT[bk * 128 + bn4];
    }
    As[0][lk4 + 0][lm] = av.x; As[0][lk4 + 1][lm] = av.y;
    As[0][lk4 + 2][lm] = av.z; As[0][lk4 + 3][lm] = av.w;
    *(float4*)&Bsm[0][bk][bn4] = bv;
    __syncthreads();

    int buf = 0;
    for (int kt = 8; kt < 1024; kt += 8) {
        int k4 = kt + lk4;
        int hf = k4 >> 7, ki = k4 & 127;
        av = *(const float4*)&g_O[(size_t)(((b << 13) + (hf << 10) + tf) << 7) + ki];
        bv = *(const float4*)&g_WuT[(kt + bk) * 128 + bn4];
        mm_step(&As[buf][0][0], &Bsm[buf][0][0], ty, tx, acc);
        buf ^= 1;
        As[buf][lk4 + 0][lm] = av.x; As[buf][lk4 + 1][lm] = av.y;
        As[buf][lk4 + 2][lm] = av.z; As[buf][lk4 + 3][lm] = av.w;
        *(float4*)&Bsm[buf][bk][bn4] = bv;
        __syncthreads();
    }
    mm_step(&As[buf][0][0], &Bsm[buf][0][0], ty, tx, acc);

#pragma unroll
    for (int i = 0; i < 8; i++) {
        int rr = rowidx(ty, i);
        float4 lo = packrow(acc[i][0], acc[i][1]);
        float4 hi = packrow(acc[i][2], acc[i][3]);
        int c0 = tx * 4;
        lo.x += bu[c0];      lo.y += bu[c0 + 1];
        lo.z += bu[c0 + 2];  lo.w += bu[c0 + 3];
        hi.x += bu[64 + c0];     hi.y += bu[64 + c0 + 1];
        hi.z += bu[64 + c0 + 2]; hi.w += bu[64 + c0 + 3];
        *(float4*)&out[(rowBase + rr) * 128 + c0]      = lo;
        *(float4*)&out[(rowBase + rr) * 128 + 64 + c0] = hi;
    }
}

// ---------------------------------------------------------------------------
extern "C" void kernel_launch(void* const* d_in, const int* in_sizes, int n_in,
                              void* d_out, int out_size) {
    const float* x  = (const float*)d_in[0];
    const float* Wq = (const float*)d_in[1];
    const float* bq = (const float*)d_in[2];
    const float* Wk = (const float*)d_in[3];
    const float* bk = (const float*)d_in[4];
    const float* Wv = (const float*)d_in[5];
    const float* bv = (const float*)d_in[6];
    const float* Wu = (const float*)d_in[7];
    const float* bu = (const float*)d_in[8];
    float* out = (float*)d_out;

    float *pWqT, *pWkT, *pWvT, *pWuT, *pQ, *pKt, *pV;
    cudaGetSymbolAddress((void**)&pWqT, g_WqT);
    cudaGetSymbolAddress((void**)&pWkT, g_WkT);
    cudaGetSymbolAddress((void**)&pWvT, g_WvT);
    cudaGetSymbolAddress((void**)&pWuT, g_WuT);
    cudaGetSymbolAddress((void**)&pQ,  g_Q);
    cudaGetSymbolAddress((void**)&pKt, g_Kt);
    cudaGetSymbolAddress((void**)&pV,  g_V);

    k_prep<<<6144, 256>>>(Wq, Wk, Wv, Wu, pWqT, pWkT, pWvT, pWuT);

    k_convQK<<<dim3(8, 64, 2), 256>>>(x, pWqT, pWkT, bq, bk, pQ, pKt);
    k_convV <<<dim3(8, 64), 256>>>(x, pWvT, bv, pV);

    k_sgemm_s<<<dim3(8, 8, 64), 256>>>();
    k_stats<<<dim3(1024, 64), 256>>>();
    k_av<<<dim3(8, 64), 256>>>();
    k_proj<<<64, 256>>>(bu, out);
}

// round 5
// speedup vs baseline: 1.6809x; 1.1870x over previous
#include <cuda_runtime.h>
#include <cuda_bf16.h>
#include <math.h>
#include <stdint.h>

// ---------------------------------------------------------------------------
// SelfAttentionConv: B=8, T=1024, K=128, H=8, TOP_K=64, KS=5
// Round 5: S=QK^T and P*V via warp-level mma.sync bf16 (HMMA) with bf16x3
// emulation and fp32 register accumulators. tcgen05 is unavailable (harness
// PTX targets compute_103 without the 'a' suffix).
// ---------------------------------------------------------------------------

#define SCALE_QK 0.2973017787506803f   // 128^-0.25

__device__ float g_S    [67108864];        // 64 * 1024 * 1024 fp32 scores
__device__ float g_O    [8388608];         // 64 * 1024 * 128
__device__ float g_stats[65536 * 4];       // per-row: thresh, rmin, off, pad
__device__ float g_WqT  [640 * 1024];
__device__ float g_WkT  [640 * 1024];
__device__ float g_WvT  [128 * 1024];
__device__ float g_WuT  [1024 * 128];
__device__ __align__(128) __nv_bfloat16 g_Qh [8388608];  // [g][ki]
__device__ __align__(128) __nv_bfloat16 g_Ql [8388608];
__device__ __align__(128) __nv_bfloat16 g_Kh [8388608];  // [g][ki]
__device__ __align__(128) __nv_bfloat16 g_Kl [8388608];
__device__ __align__(128) __nv_bfloat16 g_Vth[8388608];  // [bh][ki][s]
__device__ __align__(128) __nv_bfloat16 g_Vtl[8388608];

// ======================= mma.sync helpers ====================================
__device__ __forceinline__ uint32_t smem_u32(const void* p) {
    uint32_t a;
    asm("{ .reg .u64 t; cvta.to.shared.u64 t, %1; cvt.u32.u64 %0, t; }"
        : "=r"(a) : "l"(p));
    return a;
}
#define LDSM4(R, addr)                                                        \
    asm volatile("ldmatrix.sync.aligned.m8n8.x4.shared.b16 "                  \
                 "{%0, %1, %2, %3}, [%4];"                                    \
                 : "=r"((R)[0]), "=r"((R)[1]), "=r"((R)[2]), "=r"((R)[3])     \
                 : "r"(addr))

__device__ __forceinline__ void mma_bf16(float* d, const unsigned* a,
                                         const unsigned* b) {
    asm volatile(
        "mma.sync.aligned.m16n8k16.row.col.f32.bf16.bf16.f32 "
        "{%0, %1, %2, %3}, {%4, %5, %6, %7}, {%8, %9}, {%0, %1, %2, %3};"
        : "+f"(d[0]), "+f"(d[1]), "+f"(d[2]), "+f"(d[3])
        : "r"(a[0]), "r"(a[1]), "r"(a[2]), "r"(a[3]), "r"(b[0]), "r"(b[1]));
}

// padded smem tile: 128 rows x 128 bf16, row stride 136 elems (272 B)
// 272 B = 68 words; 68 % 32 = 4 -> row r occupies banks 4r..4r+3: LDSM clean.
#define TSTRIDE 272
#define TPLANE  34816      // 128 * 272

// smem offsets (both MMA kernels)
#define S_AH 0
#define S_AL 34816
#define S_BH 69632
#define S_BL 104448
#define S_ST 139264
#define SMEM_S_BYTES  139264
#define SMEM_AV_BYTES 141312

// ======================= FFMA2 helpers (convs / proj) ========================
__device__ __forceinline__ unsigned long long fma2(unsigned long long a,
                                                   unsigned long long b,
                                                   unsigned long long c) {
    unsigned long long d;
    asm("fma.rn.f32x2 %0, %1, %2, %3;" : "=l"(d) : "l"(a), "l"(b), "l"(c));
    return d;
}
__device__ __forceinline__ float2 up2(unsigned long long v) {
    float2 r;
    asm("mov.b64 {%0, %1}, %2;" : "=f"(r.x), "=f"(r.y) : "l"(v));
    return r;
}
__device__ __forceinline__ unsigned long long dup2(float a) {
    unsigned long long d;
    asm("mov.b64 %0, {%1, %1};" : "=l"(d) : "f"(a));
    return d;
}
__device__ __forceinline__ void mm_step(const float* __restrict__ As,
                                        const float* __restrict__ Bs,
                                        int ty, int tx,
                                        unsigned long long acc[8][4]) {
#pragma unroll
    for (int kk = 0; kk < 8; kk++) {
        const float* ar = As + kk * 128;
        const float* br = Bs + kk * 128;
        float4 x0 = *(const float4*)(ar + ty * 4);
        float4 x1 = *(const float4*)(ar + 64 + ty * 4);
        ulonglong2 b01 = *(const ulonglong2*)(br + tx * 4);
        ulonglong2 b23 = *(const ulonglong2*)(br + 64 + tx * 4);
        unsigned long long a[8] = {dup2(x0.x), dup2(x0.y), dup2(x0.z), dup2(x0.w),
                                   dup2(x1.x), dup2(x1.y), dup2(x1.z), dup2(x1.w)};
        unsigned long long b[4] = {b01.x, b01.y, b23.x, b23.y};
#pragma unroll
        for (int i = 0; i < 8; i++)
#pragma unroll
            for (int p = 0; p < 4; p++)
                acc[i][p] = fma2(a[i], b[p], acc[i][p]);
    }
}
__device__ __forceinline__ int rowidx(int ty, int i) {
    return (i < 4) ? (ty * 4 + i) : (64 + ty * 4 + i - 4);
}
__device__ __forceinline__ float4 packrow(unsigned long long p0,
                                          unsigned long long p1) {
    float2 a = up2(p0), b = up2(p1);
    return make_float4(a.x, a.y, b.x, b.y);
}

// ---------------- merged weight prep ----------------------------------------
__global__ void k_prep(const float* __restrict__ Wq, const float* __restrict__ Wk,
                       const float* __restrict__ Wv, const float* __restrict__ Wu,
                       float* __restrict__ WqT, float* __restrict__ WkT,
                       float* __restrict__ WvT, float* __restrict__ WuT) {
    int idx = blockIdx.x * 256 + threadIdx.x;
    if (idx < 655360) {
        int k = idx >> 10, c = idx & 1023;
        int j = k >> 7, ci = k & 127;
        WqT[idx] = Wq[(c * 128 + ci) * 5 + j];
    } else if (idx < 1310720) {
        int i1 = idx - 655360;
        int k = i1 >> 10, c = i1 & 1023;
        int j = k >> 7, ci = k & 127;
        WkT[i1] = Wk[(c * 128 + ci) * 5 + j];
    } else if (idx < 1441792) {
        int i2 = idx - 1310720;
        int ci = i2 >> 10, c = i2 & 1023;
        WvT[i2] = Wv[c * 128 + ci];
    } else {
        int i3 = idx - 1441792;
        int c = i3 >> 7, n = i3 & 127;
        WuT[i3] = Wu[n * 1024 + c];
    }
}

// ---------------- conv-as-GEMM, bf16 hi/lo epilogue --------------------------
__device__ __forceinline__ void conv_body(
    const float* __restrict__ x, const float* __restrict__ Wt,
    const float* __restrict__ bias,
    __nv_bfloat16* __restrict__ hiO, __nv_bfloat16* __restrict__ loO,
    int Kd, int pad, float scale, int transOut,
    float As[2][8][128], float Bsm[2][8][128])
{
    unsigned long long acc[8][4];
#pragma unroll
    for (int i = 0; i < 8; i++)
#pragma unroll
        for (int p = 0; p < 4; p++) acc[i][p] = 0ull;

    const int tid = threadIdx.x;
    const int ty = tid >> 4, tx = tid & 15;
    const int rowBase = blockIdx.y * 128;
    const int colBase = blockIdx.x * 128;
    const int lm = tid >> 1, lk4 = (tid & 1) * 4;
    const int bk = tid >> 5, bn4 = (tid & 31) * 4;
    const int m = rowBase + lm;
    const int b = m >> 10, t = m & 1023;

    float4 av, bv;
    {
        int j = lk4 >> 7, ci = lk4 & 127;
        int tt = t + j - pad;
        av = make_float4(0.f, 0.f, 0.f, 0.f);
        if (tt >= 0) av = *(const float4*)&x[(((b << 10) | tt) << 7) + ci];
        bv = *(const float4*)&Wt[bk * 1024 + colBase + bn4];
    }
    As[0][lk4 + 0][lm] = av.x; As[0][lk4 + 1][lm] = av.y;
    As[0][lk4 + 2][lm] = av.z; As[0][lk4 + 3][lm] = av.w;
    *(float4*)&Bsm[0][bk][bn4] = bv;
    __syncthreads();

    int buf = 0;
    for (int kt = 8; kt < Kd; kt += 8) {
        int k4 = kt + lk4;
        int j = k4 >> 7, ci = k4 & 127;
        int tt = t + j - pad;
        av = make_float4(0.f, 0.f, 0.f, 0.f);
        if (tt >= 0) av = *(const float4*)&x[(((b << 10) | tt) << 7) + ci];
        bv = *(const float4*)&Wt[(kt + bk) * 1024 + colBase + bn4];

        mm_step(&As[buf][0][0], &Bsm[buf][0][0], ty, tx, acc);
        buf ^= 1;
        As[buf][lk4 + 0][lm] = av.x; As[buf][lk4 + 1][lm] = av.y;
        As[buf][lk4 + 2][lm] = av.z; As[buf][lk4 + 3][lm] = av.w;
        *(float4*)&Bsm[buf][bk][bn4] = bv;
        __syncthreads();
    }
    mm_step(&As[buf][0][0], &Bsm[buf][0][0], ty, tx, acc);

#pragma unroll
    for (int i = 0; i < 8; i++) {
        int rr = rowidx(ty, i);
        int mm = rowBase + rr;
        int b2 = mm >> 10, t2 = mm & 1023;
        int gb = (b2 << 13) | (t2 << 3);
#pragma unroll
        for (int p = 0; p < 4; p++) {
            float2 v = up2(acc[i][p]);
            int cc0 = colBase + ((p >> 1) ? 64 : 0) + tx * 4 + (p & 1) * 2;
#pragma unroll
            for (int e = 0; e < 2; e++) {
                int cg = cc0 + e;
                float val = ((e ? v.y : v.x) + bias[cg]) * scale;
                int hh = cg & 7, ki = cg >> 3;
                int row = gb | hh;
                __nv_bfloat16 h = __float2bfloat16(val);
                __nv_bfloat16 l = __float2bfloat16(val - __bfloat162float(h));
                size_t idx = transOut
                    ? (size_t)((row >> 10) * 128 + ki) * 1024 + (row & 1023)
                    : (size_t)row * 128 + ki;
                hiO[idx] = h;
                loO[idx] = l;
            }
        }
    }
}

__global__ __launch_bounds__(256, 2) void k_convQK(
    const float* __restrict__ x,
    const float* __restrict__ WqT, const float* __restrict__ WkT,
    const float* __restrict__ bq, const float* __restrict__ bk)
{
    __shared__ __align__(16) float As [2][8][128];
    __shared__ __align__(16) float Bsm[2][8][128];
    if (blockIdx.z == 0)
        conv_body(x, WqT, bq, g_Qh, g_Ql, 640, 4, SCALE_QK, 0, As, Bsm);
    else
        conv_body(x, WkT, bk, g_Kh, g_Kl, 640, 4, SCALE_QK, 0, As, Bsm);
}

__global__ __launch_bounds__(256, 2) void k_convV(
    const float* __restrict__ x, const float* __restrict__ WvT,
    const float* __restrict__ bv)
{
    __shared__ __align__(16) float As [2][8][128];
    __shared__ __align__(16) float Bsm[2][8][128];
    conv_body(x, WvT, bv, g_Vth, g_Vtl, 128, 0, 1.0f, 1, As, Bsm);
}

// ---------------- S = Q K^T via mma.sync bf16x3 ------------------------------
__global__ __launch_bounds__(256, 1) void k_s_mma() {
    extern __shared__ char sm[];
    const int tid = threadIdx.x, lane = tid & 31, wid = tid >> 5;
    const int nt = blockIdx.x, mt = blockIdx.y, bh = blockIdx.z;
    const uint32_t smb = smem_u32(sm);

    const __nv_bfloat16* Ah = g_Qh + ((size_t)((bh << 10) + mt * 128)) * 128;
    const __nv_bfloat16* Al = g_Ql + ((size_t)((bh << 10) + mt * 128)) * 128;
    const __nv_bfloat16* Bh = g_Kh + ((size_t)((bh << 10) + nt * 128)) * 128;
    const __nv_bfloat16* Bl = g_Kl + ((size_t)((bh << 10) + nt * 128)) * 128;
#pragma unroll
    for (int i = 0; i < 8; i++) {
        int c = i * 256 + tid, r = c >> 4, j = c & 15;
        int dst = r * TSTRIDE + j * 16;
        *(uint4*)(sm + S_AH + dst) = ((const uint4*)(Ah + (size_t)r * 128))[j];
        *(uint4*)(sm + S_AL + dst) = ((const uint4*)(Al + (size_t)r * 128))[j];
        *(uint4*)(sm + S_BH + dst) = ((const uint4*)(Bh + (size_t)r * 128))[j];
        *(uint4*)(sm + S_BL + dst) = ((const uint4*)(Bl + (size_t)r * 128))[j];
    }
    __syncthreads();

    const int wm = wid >> 1, wn = wid & 1;
    float acc[2][8][4];
#pragma unroll
    for (int i = 0; i < 2; i++)
#pragma unroll
        for (int j = 0; j < 8; j++)
#pragma unroll
            for (int e = 0; e < 4; e++) acc[i][j][e] = 0.f;

    // ldmatrix lane address patterns
    const int aRow = wm * 32 + (lane & 7) + ((lane >> 3) & 1) * 8;
    const int aKb  = (lane >> 4) * 16;              // khalf byte offset
    const int bRow = wn * 64 + ((lane >> 4) & 1) * 8 + (lane & 7);
    const int bKb  = ((lane >> 3) & 1) * 16;

    const uint32_t aH = smb + S_AH + aRow * TSTRIDE + aKb;
    const uint32_t aL = smb + S_AL + aRow * TSTRIDE + aKb;
    const uint32_t bH = smb + S_BH + bRow * TSTRIDE + bKb;
    const uint32_t bL = smb + S_BL + bRow * TSTRIDE + bKb;

#pragma unroll
    for (int k = 0; k < 8; k++) {
        const int kb = k * 32;                       // 16 bf16 = 32 bytes
        unsigned ah[2][4], al[2][4], bhr[8][2], blr[8][2];
#pragma unroll
        for (int mf = 0; mf < 2; mf++) {
            LDSM4(ah[mf], aH + mf * 16 * TSTRIDE + kb);
            LDSM4(al[mf], aL + mf * 16 * TSTRIDE + kb);
        }
#pragma unroll
        for (int g = 0; g < 4; g++) {
            LDSM4(&bhr[2 * g][0], bH + g * 16 * TSTRIDE + kb);
            LDSM4(&blr[2 * g][0], bL + g * 16 * TSTRIDE + kb);
        }
#pragma unroll
        for (int mf = 0; mf < 2; mf++)
#pragma unroll
            for (int nf = 0; nf < 8; nf++) {
                mma_bf16(acc[mf][nf], ah[mf], bhr[nf]);
                mma_bf16(acc[mf][nf], ah[mf], blr[nf]);
                mma_bf16(acc[mf][nf], al[mf], bhr[nf]);
            }
    }

    // epilogue -> g_S
    float* C = g_S + ((size_t)bh << 20);
    const int r0 = mt * 128 + wm * 32 + (lane >> 2);
    const int c0 = nt * 128 + wn * 64 + (lane & 3) * 2;
#pragma unroll
    for (int mf = 0; mf < 2; mf++)
#pragma unroll
        for (int nf = 0; nf < 8; nf++) {
            int rr = r0 + mf * 16, cc = c0 + nf * 8;
            *(float2*)&C[(size_t)rr * 1024 + cc] =
                make_float2(acc[mf][nf][0], acc[mf][nf][1]);
            *(float2*)&C[(size_t)(rr + 8) * 1024 + cc] =
                make_float2(acc[mf][nf][2], acc[mf][nf][3]);
        }
}

// ---------------- per-row stats: topk threshold, rmin, softmax offset -------
__global__ __launch_bounds__(256) void k_stats() {
    const int t  = blockIdx.x;
    const int bh = blockIdx.y;
    const float* row = g_S + ((size_t)bh << 20) + ((size_t)t << 10);
    const int tid = threadIdx.x, lane = tid & 31, wid = tid >> 5;

    float4 v4 = ((const float4*)row)[tid];
    float vals[4] = { v4.x, v4.y, v4.z, v4.w };
    unsigned key[4];
#pragma unroll
    for (int i = 0; i < 4; i++) {
        unsigned u = __float_as_uint(vals[i]);
        key[i] = (u & 0x80000000u) ? ~u : (u | 0x80000000u);
    }

    __shared__ float redf[8];
    __shared__ unsigned hist[256];
    __shared__ unsigned wsum[8];
    __shared__ unsigned sh_sel, sh_need;

    float lmin = fminf(fminf(vals[0], vals[1]), fminf(vals[2], vals[3]));
#pragma unroll
    for (int off = 16; off; off >>= 1)
        lmin = fminf(lmin, __shfl_xor_sync(0xffffffffu, lmin, off));
    if (lane == 0) redf[wid] = lmin;
    __syncthreads();
    float rmin = redf[0];
#pragma unroll
    for (int i = 1; i < 8; i++) rmin = fminf(rmin, redf[i]);

    unsigned prefix = 0u, need = 64u;
#pragma unroll
    for (int pass = 0; pass < 4; pass++) {
        const int shift = 24 - pass * 8;
        hist[tid] = 0u;
        __syncthreads();
        unsigned mask = (pass == 0) ? 0u : (0xFFFFFFFFu << (shift + 8));
#pragma unroll
        for (int i = 0; i < 4; i++)
            if ((key[i] & mask) == prefix)
                atomicAdd(&hist[(key[i] >> shift) & 255u], 1u);
        __syncthreads();
        unsigned h = hist[tid];
        unsigned s = h;
#pragma unroll
        for (int off = 1; off < 32; off <<= 1) {
            unsigned v = __shfl_down_sync(0xffffffffu, s, off);
            if (lane + off < 32) s += v;
        }
        if (lane == 0) wsum[wid] = s;
        __syncthreads();
        unsigned tail = 0u;
        for (int w = wid + 1; w < 8; w++) tail += wsum[w];
        unsigned cum = s + tail;
        unsigned cumN = cum - h;
        if (cum >= need && cumN < need) { sh_sel = (unsigned)tid; sh_need = need - cumN; }
        __syncthreads();
        prefix |= (sh_sel << shift);
        need = sh_need;
        __syncthreads();
    }
    unsigned tu = (prefix & 0x80000000u) ? (prefix & 0x7FFFFFFFu) : ~prefix;
    const float thresh = __uint_as_float(tu);

    float p[4];
    float lmax = -1e30f;
#pragma unroll
    for (int i = 0; i < 4; i++) {
        int s = tid * 4 + i;
        float pv = (vals[i] >= thresh) ? vals[i] : rmin;
        p[i] = pv;
        if (s <= t) lmax = fmaxf(lmax, pv);
    }
#pragma unroll
    for (int off = 16; off; off >>= 1)
        lmax = fmaxf(lmax, __shfl_xor_sync(0xffffffffu, lmax, off));
    if (lane == 0) redf[wid] = lmax;
    __syncthreads();
    float mx = redf[0];
#pragma unroll
    for (int i = 1; i < 8; i++) mx = fmaxf(mx, redf[i]);
    __syncthreads();

    float lsum = 0.f;
#pragma unroll
    for (int i = 0; i < 4; i++) {
        int s = tid * 4 + i;
        if (s <= t) lsum += __expf(p[i] - mx);
    }
#pragma unroll
    for (int off = 16; off; off >>= 1)
        lsum += __shfl_xor_sync(0xffffffffu, lsum, off);
    if (lane == 0) redf[wid] = lsum;
    __syncthreads();
    if (tid == 0) {
        float tot = 0.f;
#pragma unroll
        for (int i = 0; i < 8; i++) tot += redf[i];
        float off0 = mx + __logf(tot);
        ((float4*)g_stats)[(bh << 10) + t] = make_float4(thresh, rmin, off0, 0.f);
    }
}

// ---------------- O = P V via mma.sync bf16x3 (causal chunked) ---------------
__global__ __launch_bounds__(256, 1) void k_av_mma() {
    extern __shared__ char sm[];
    const int tid = threadIdx.x, lane = tid & 31, wid = tid >> 5;
    const int mt = blockIdx.x, bh = blockIdx.y;
    const int rowBase = mt * 128;
    const uint32_t smb = smem_u32(sm);

    // cache row stats (128 x float4)
    if (tid < 128)
        ((float4*)(sm + S_ST))[tid] =
            ((const float4*)g_stats)[(bh << 10) + rowBase + tid];

    const int wm = wid >> 1, wn = wid & 1;
    float acc[2][8][4];
#pragma unroll
    for (int i = 0; i < 2; i++)
#pragma unroll
        for (int j = 0; j < 8; j++)
#pragma unroll
            for (int e = 0; e < 4; e++) acc[i][j][e] = 0.f;

    const int aRow = wm * 32 + (lane & 7) + ((lane >> 3) & 1) * 8;
    const int aKb  = (lane >> 4) * 16;
    const int bRow = wn * 64 + ((lane >> 4) & 1) * 8 + (lane & 7);
    const int bKb  = ((lane >> 3) & 1) * 16;
    const uint32_t pH = smb + S_AH + aRow * TSTRIDE + aKb;
    const uint32_t pL = smb + S_AL + aRow * TSTRIDE + aKb;
    const uint32_t vH = smb + S_BH + bRow * TSTRIDE + bKb;
    const uint32_t vL = smb + S_BL + bRow * TSTRIDE + bKb;

    const int nChunks = mt + 1;
    for (int c = 0; c < nChunks; c++) {
        const int kt = c * 128;
        __syncthreads();   // smem reuse guard (also covers stats on iter 0)

        // transform S chunk -> P (threshold + causal + exp) -> bf16 hi/lo
#pragma unroll
        for (int i = 0; i < 16; i++) {
            int idx4 = i * 256 + tid;
            int r = idx4 >> 5;
            int s4 = (idx4 & 31) * 4;
            float4 st = ((const float4*)(sm + S_ST))[r];
            const float th = st.x, rm = st.y, off0 = st.z;
            const int tg = rowBase + r;
            float4 v = *(const float4*)&g_S[((size_t)bh << 20)
                                            + (size_t)tg * 1024 + kt + s4];
            float pv[4] = { v.x, v.y, v.z, v.w };
            __nv_bfloat16 hb[4];
#pragma unroll
            for (int j = 0; j < 4; j++) {
                int sg = kt + s4 + j;
                float p = (pv[j] >= th) ? pv[j] : rm;
                p = (sg <= tg) ? __expf(p - off0) : 0.f;
                pv[j] = p;
                hb[j] = __float2bfloat16(p);
            }
            unsigned lo01, lo23;
            {
                __nv_bfloat162 l01 = __floats2bfloat162_rn(
                    pv[0] - __bfloat162float(hb[0]), pv[1] - __bfloat162float(hb[1]));
                __nv_bfloat162 l23 = __floats2bfloat162_rn(
                    pv[2] - __bfloat162float(hb[2]), pv[3] - __bfloat162float(hb[3]));
                lo01 = *(unsigned*)&l01;
                lo23 = *(unsigned*)&l23;
            }
            __nv_bfloat162 h01 = __halves2bfloat162(hb[0], hb[1]);
            __nv_bfloat162 h23 = __halves2bfloat162(hb[2], hb[3]);
            int off = r * TSTRIDE + s4 * 2;
            *(uint2*)(sm + S_AH + off) = make_uint2(*(unsigned*)&h01, *(unsigned*)&h23);
            *(uint2*)(sm + S_AL + off) = make_uint2(lo01, lo23);
        }
        // V chunk (B operand: rows = ki, cols = s)
#pragma unroll
        for (int i = 0; i < 8; i++) {
            int cc = i * 256 + tid;
            int r = cc >> 4, j = cc & 15;
            int dst = r * TSTRIDE + j * 16;
            *(uint4*)(sm + S_BH + dst) =
                ((const uint4*)(g_Vth + (size_t)(bh * 128 + r) * 1024 + kt))[j];
            *(uint4*)(sm + S_BL + dst) =
                ((const uint4*)(g_Vtl + (size_t)(bh * 128 + r) * 1024 + kt))[j];
        }
        __syncthreads();

#pragma unroll
        for (int k = 0; k < 8; k++) {
            const int kb = k * 32;
            unsigned ah[2][4], al[2][4], bhr[8][2], blr[8][2];
#pragma unroll
            for (int mf = 0; mf < 2; mf++) {
                LDSM4(ah[mf], pH + mf * 16 * TSTRIDE + kb);
                LDSM4(al[mf], pL + mf * 16 * TSTRIDE + kb);
            }
#pragma unroll
            for (int g = 0; g < 4; g++) {
                LDSM4(&bhr[2 * g][0], vH + g * 16 * TSTRIDE + kb);
                LDSM4(&blr[2 * g][0], vL + g * 16 * TSTRIDE + kb);
            }
#pragma unroll
            for (int mf = 0; mf < 2; mf++)
#pragma unroll
                for (int nf = 0; nf < 8; nf++) {
                    mma_bf16(acc[mf][nf], ah[mf], bhr[nf]);
                    mma_bf16(acc[mf][nf], ah[mf], blr[nf]);
                    mma_bf16(acc[mf][nf], al[mf], bhr[nf]);
                }
        }
    }

    // epilogue -> g_O  (rows = t, cols = ki)
    const int r0 = (bh << 10) + rowBase + wm * 32 + (lane >> 2);
    const int c0 = wn * 64 + (lane & 3) * 2;
#pragma unroll
    for (int mf = 0; mf < 2; mf++)
#pragma unroll
        for (int nf = 0; nf < 8; nf++) {
            int rr = r0 + mf * 16, cc = c0 + nf * 8;
            *(float2*)&g_O[(size_t)rr * 128 + cc] =
                make_float2(acc[mf][nf][0], acc[mf][nf][1]);
            *(float2*)&g_O[(size_t)(rr + 8) * 128 + cc] =
                make_float2(acc[mf][nf][2], acc[mf][nf][3]);
        }
}

// ---------------- final projection (FFMA2) -----------------------------------
__global__ __launch_bounds__(256, 2) void k_proj(const float* __restrict__ bu,
                                                 float* __restrict__ out) {
    __shared__ __align__(16) float As [2][8][128];
    __shared__ __align__(16) float Bsm[2][8][128];
    unsigned long long acc[8][4];
#pragma unroll
    for (int i = 0; i < 8; i++)
#pragma unroll
        for (int p = 0; p < 4; p++) acc[i][p] = 0ull;

    const int tid = threadIdx.x;
    const int ty = tid >> 4, tx = tid & 15;
    const int rowBase = blockIdx.x * 128;
    const int lm = tid >> 1, lk4 = (tid & 1) * 4;
    const int bk = tid >> 5, bn4 = (tid & 31) * 4;
    const int m = rowBase + lm;
    const int b = m >> 10, tf = m & 1023;

    float4 av, bv;
    {
        int hf = lk4 >> 7, ki = lk4 & 127;
        av = *(const float4*)&g_O[(size_t)(((b << 13) + (hf << 10) + tf) << 7) + ki];
        bv = *(const float4*)&g_WuT[bk * 128 + bn4];
    }
    As[0][lk4 + 0][lm] = av.x; As[0][lk4 + 1][lm] = av.y;
    As[0][lk4 + 2][lm] = av.z; As[0][lk4 + 3][lm] = av.w;
    *(float4*)&Bsm[0][bk][bn4] = bv;
    __syncthreads();

    int buf = 0;
    for (int kt = 8; kt < 1024; kt += 8) {
        int k4 = kt + lk4;
        int hf = k4 >> 7, ki = k4 & 127;
        av = *(const float4*)&g_O[(size_t)(((b << 13) + (hf << 10) + tf) << 7) + ki];
        bv = *(const float4*)&g_WuT[(kt + bk) * 128 + bn4];
        mm_step(&As[buf][0][0], &Bsm[buf][0][0], ty, tx, acc);
        buf ^= 1;
        As[buf][lk4 + 0][lm] = av.x; As[buf][lk4 + 1][lm] = av.y;
        As[buf][lk4 + 2][lm] = av.z; As[buf][lk4 + 3][lm] = av.w;
        *(float4*)&Bsm[buf][bk][bn4] = bv;
        __syncthreads();
    }
    mm_step(&As[buf][0][0], &Bsm[buf][0][0], ty, tx, acc);

#pragma unroll
    for (int i = 0; i < 8; i++) {
        int rr = rowidx(ty, i);
        float4 lo = packrow(acc[i][0], acc[i][1]);
        float4 hi = packrow(acc[i][2], acc[i][3]);
        int c0 = tx * 4;
        lo.x += bu[c0];      lo.y += bu[c0 + 1];
        lo.z += bu[c0 + 2];  lo.w += bu[c0 + 3];
        hi.x += bu[64 + c0];     hi.y += bu[64 + c0 + 1];
        hi.z += bu[64 + c0 + 2]; hi.w += bu[64 + c0 + 3];
        *(float4*)&out[(rowBase + rr) * 128 + c0]      = lo;
        *(float4*)&out[(rowBase + rr) * 128 + 64 + c0] = hi;
    }
}

// ---------------------------------------------------------------------------
extern "C" void kernel_launch(void* const* d_in, const int* in_sizes, int n_in,
                              void* d_out, int out_size) {
    const float* x  = (const float*)d_in[0];
    const float* Wq = (const float*)d_in[1];
    const float* bq = (const float*)d_in[2];
    const float* Wk = (const float*)d_in[3];
    const float* bk = (const float*)d_in[4];
    const float* Wv = (const float*)d_in[5];
    const float* bv = (const float*)d_in[6];
    const float* Wu = (const float*)d_in[7];
    const float* bu = (const float*)d_in[8];
    float* out = (float*)d_out;

    float *pWqT, *pWkT, *pWvT, *pWuT;
    cudaGetSymbolAddress((void**)&pWqT, g_WqT);
    cudaGetSymbolAddress((void**)&pWkT, g_WkT);
    cudaGetSymbolAddress((void**)&pWvT, g_WvT);
    cudaGetSymbolAddress((void**)&pWuT, g_WuT);

    cudaFuncSetAttribute(k_s_mma,
        cudaFuncAttributeMaxDynamicSharedMemorySize, SMEM_S_BYTES);
    cudaFuncSetAttribute(k_av_mma,
        cudaFuncAttributeMaxDynamicSharedMemorySize, SMEM_AV_BYTES);

    k_prep<<<6144, 256>>>(Wq, Wk, Wv, Wu, pWqT, pWkT, pWvT, pWuT);

    k_convQK<<<dim3(8, 64, 2), 256>>>(x, pWqT, pWkT, bq, bk);
    k_convV <<<dim3(8, 64), 256>>>(x, pWvT, bv);

    k_s_mma<<<dim3(8, 8, 64), 256, SMEM_S_BYTES>>>();
    k_stats<<<dim3(1024, 64), 256>>>();
    k_av_mma<<<dim3(8, 64), 256, SMEM_AV_BYTES>>>();
    k_proj<<<64, 256>>>(bu, out);
}